// round 8
// baseline (speedup 1.0000x reference)
#include <cuda_runtime.h>
#include <cuda_bf16.h>
#include <stdint.h>

// Inputs (metadata order):
//   d_in[0]: inputs_t  int32  [1, n_source]   (n_source = 17400)
//   d_in[1]: indices   int32  [N_SYN, 2]  -> (post, pre) per row
//   d_in[2]: weights   float32 [N_SYN]
//   d_in[3]: n_post    (scalar; we use out_size instead)
// Output: float32 [1, n_post]
//
// Model (round 6/7): duration is pinned by the L2/LTS op wall:
//   11.25M stream-read sectors + 15M RED.ADD.F32 (~1.7 LTS-cyc each)
//   ~= 36.7M LTS-cycles / 184 partitions ~= 108us @NAT. The scatter kernel
//   is at that wall; this round removes launch-serialization overhead via
//   PDL (zero kernel -> scatter overlap).

// Zero kernel: 148 blocks x 256 threads, float4 grid-stride, then trigger
// programmatic launch completion so the scatter (launched with PDL) can
// begin its ramp while this grid drains.
__global__ void __launch_bounds__(256) zero_pdl_kernel(float4* __restrict__ out4,
                                                      int n4,
                                                      float* __restrict__ out,
                                                      int rem_start, int n)
{
    int stride = gridDim.x * blockDim.x;
    for (int i = blockIdx.x * blockDim.x + threadIdx.x; i < n4; i += stride)
        out4[i] = make_float4(0.f, 0.f, 0.f, 0.f);
    // tail elements (out_size % 4), tiny
    for (int i = rem_start + blockIdx.x * blockDim.x + threadIdx.x; i < n;
         i += stride)
        out[i] = 0.0f;
    __threadfence();
    cudaTriggerProgrammaticLaunchCompletion();
}

// 4 synapses per thread: two int4 index loads + one float4 weight load.
// Activity loads hoisted ahead of the REDs; atomics predicated (~50% skipped).
// Waits on the PDL grid dependency before touching `out`.
__global__ void __launch_bounds__(256) scatter4_kernel(
    const int*    __restrict__ act,    // inputs_t, n_source ints (L1/L2-resident)
    const int4*   __restrict__ idx4,   // (post0,pre0,post1,pre1) pairs
    const float4* __restrict__ w4,
    float*        __restrict__ out,
    int n_quads)                        // n_syn / 4
{
    int i = blockIdx.x * blockDim.x + threadIdx.x;
    if (i >= n_quads) {
        cudaGridDependencySynchronize();
        return;
    }

    // Front-batch all loads (inputs are independent of the zeroing).
    int4   a  = idx4[2 * i];
    int4   b  = idx4[2 * i + 1];
    float4 wv = w4[i];

    int act0 = __ldg(act + a.y);
    int act1 = __ldg(act + a.w);
    int act2 = __ldg(act + b.y);
    int act3 = __ldg(act + b.w);

    // Output must be zeroed before any RED lands.
    cudaGridDependencySynchronize();

    if (act0 > 0) atomicAdd(out + a.x, wv.x);
    if (act1 > 0) atomicAdd(out + a.z, wv.y);
    if (act2 > 0) atomicAdd(out + b.x, wv.z);
    if (act3 > 0) atomicAdd(out + b.z, wv.w);
}

// Tail for n_syn not divisible by 4 (not launched for N_SYN=30M).
__global__ void scatter_tail_kernel(
    const int*  __restrict__ act,
    const int2* __restrict__ idx2,
    const float* __restrict__ w,
    float*       __restrict__ out,
    int start, int n_syn)
{
    int i = start + blockIdx.x * blockDim.x + threadIdx.x;
    if (i >= n_syn) return;
    int2 p = idx2[i];
    if (__ldg(act + p.y) > 0) atomicAdd(out + p.x, w[i]);
}

extern "C" void kernel_launch(void* const* d_in, const int* in_sizes, int n_in,
                              void* d_out, int out_size) {
    const int*   act     = (const int*)d_in[0];
    const int*   indices = (const int*)d_in[1];
    const float* weights = (const float*)d_in[2];
    float*       out     = (float*)d_out;

    const int n_syn = in_sizes[2];   // weights element count

    // Zero the output (primary grid of the PDL pair).
    const int n4 = out_size / 4;
    zero_pdl_kernel<<<148, 256>>>((float4*)out, n4, out, n4 * 4, out_size);

    // Scatter, launched with programmatic stream serialization: its blocks
    // launch while the zero grid drains; cudaGridDependencySynchronize()
    // inside gates the atomics on zero completion.
    const int n_quads = n_syn / 4;
    if (n_quads > 0) {
        cudaLaunchConfig_t cfg = {};
        cfg.gridDim  = dim3((n_quads + 255) / 256);
        cfg.blockDim = dim3(256);
        cfg.stream   = 0;
        cudaLaunchAttribute attr[1];
        attr[0].id = cudaLaunchAttributeProgrammaticStreamSerialization;
        attr[0].val.programmaticStreamSerializationAllowed = 1;
        cfg.attrs    = attr;
        cfg.numAttrs = 1;
        cudaLaunchKernelEx(&cfg, scatter4_kernel,
                           act, (const int4*)indices, (const float4*)weights,
                           out, n_quads);
    }

    const int done = n_quads * 4;
    if (done < n_syn) {           // not taken for n_syn = 30M
        int rem = n_syn - done;
        int threads = 256;
        int blocks  = (rem + threads - 1) / threads;
        scatter_tail_kernel<<<blocks, threads>>>(
            act, (const int2*)indices, weights, out, done, n_syn);
    }
}

// round 11
// speedup vs baseline: 1.3322x; 1.3322x over previous
#include <cuda_runtime.h>
#include <cuda_bf16.h>
#include <stdint.h>

// Inputs (metadata order):
//   d_in[0]: inputs_t  int32  [1, n_source]   (n_source = 17400)
//   d_in[1]: indices   int32  [N_SYN, 2]  -> (post, pre) per row
//   d_in[2]: weights   float32 [N_SYN]
//   d_in[3]: n_post    (scalar; we use out_size instead)
// Output: float32 [1, n_post]
//
// Final model (rounds 2-8): the scatter is pinned at ~107.6us by the L2/LTS
// op wall (11.25M stream-read sectors + ~15M predicated RED.ADD.F32).
// Measured alternatives: smem activity bitmask 110.5us, TMA double-buffer
// ~115us, warp-specialized 4-stage ring ~120us, PDL-gated zero ~145us.
// The minimal LDG kernel + graph memset node is the fastest configuration.

// 4 synapses per thread: two int4 index loads + one float4 weight load.
// Activity loads hoisted ahead of the REDs; atomics predicated (~50% skipped).
__global__ void __launch_bounds__(256) scatter4_kernel(
    const int*    __restrict__ act,    // inputs_t, n_source ints (L1/L2-resident)
    const int4*   __restrict__ idx4,   // (post0,pre0,post1,pre1) pairs
    const float4* __restrict__ w4,
    float*        __restrict__ out,
    int n_quads)                        // n_syn / 4
{
    int i = blockIdx.x * blockDim.x + threadIdx.x;
    if (i >= n_quads) return;

    int4   a  = idx4[2 * i];
    int4   b  = idx4[2 * i + 1];
    float4 wv = w4[i];

    // Front-batch the gather loads so all four are in flight before any RED.
    int act0 = __ldg(act + a.y);
    int act1 = __ldg(act + a.w);
    int act2 = __ldg(act + b.y);
    int act3 = __ldg(act + b.w);

    if (act0 > 0) atomicAdd(out + a.x, wv.x);
    if (act1 > 0) atomicAdd(out + a.z, wv.y);
    if (act2 > 0) atomicAdd(out + b.x, wv.z);
    if (act3 > 0) atomicAdd(out + b.z, wv.w);
}

// Tail for n_syn not divisible by 4 (not launched for N_SYN=30M).
__global__ void scatter_tail_kernel(
    const int*  __restrict__ act,
    const int2* __restrict__ idx2,
    const float* __restrict__ w,
    float*       __restrict__ out,
    int start, int n_syn)
{
    int i = start + blockIdx.x * blockDim.x + threadIdx.x;
    if (i >= n_syn) return;
    int2 p = idx2[i];
    if (__ldg(act + p.y) > 0) atomicAdd(out + p.x, w[i]);
}

extern "C" void kernel_launch(void* const* d_in, const int* in_sizes, int n_in,
                              void* d_out, int out_size) {
    const int*   act     = (const int*)d_in[0];
    const int*   indices = (const int*)d_in[1];
    const float* weights = (const float*)d_in[2];
    float*       out     = (float*)d_out;

    const int n_syn = in_sizes[2];   // weights element count

    // Zero the output with a memset node (graph-capturable, no SM launch).
    cudaMemsetAsync(out, 0, (size_t)out_size * sizeof(float), 0);

    const int n_quads = n_syn / 4;
    if (n_quads > 0) {
        int threads = 256;
        int blocks  = (n_quads + threads - 1) / threads;
        scatter4_kernel<<<blocks, threads>>>(
            act, (const int4*)indices, (const float4*)weights, out, n_quads);
    }

    const int done = n_quads * 4;
    if (done < n_syn) {           // not taken for n_syn = 30M
        int rem = n_syn - done;
        int threads = 256;
        int blocks  = (rem + threads - 1) / threads;
        scatter_tail_kernel<<<blocks, threads>>>(
            act, (const int2*)indices, weights, out, done, n_syn);
    }
}